// round 14
// baseline (speedup 1.0000x reference)
#include <cuda_runtime.h>
#include <cuda_fp16.h>
#include <math.h>
#include <stdint.h>

#define B_   2
#define S_   1024
#define HID_ 2048
#define NH_  16
#define NKV_ 2
#define HD_  128
#define G_   (NH_/NKV_)
#define TOK  (B_*S_)

#define KP   2048
#define NQKV 2560

// ---------------- scratch ----------------
#define OFF_EFF  0
#define OFF_BIAS 4
#define OFF_APK  2564
#define OFF_BQKV 2099716
#define OFF_BOW  4721156
#define OFF_QPK  6818308
#define OFF_KPK  8915460
#define OFF_VPK  9177604
#define SCRATCH_F 9439748
__device__ __align__(256) float g_scratch[SCRATCH_F];

// ---------------- helpers ----------------
__device__ __forceinline__ uint32_t smem_u32(const void* p) {
    uint32_t a;
    asm("{ .reg .u64 t; cvta.to.shared.u64 t, %1; cvt.u32.u64 %0, t; }" : "=r"(a) : "l"(p));
    return a;
}
__device__ __forceinline__ uint32_t pack2(unsigned short a, unsigned short b) {
    return (uint32_t)a | ((uint32_t)b << 16);
}
__device__ __forceinline__ void cp_async16(uint32_t saddr, const void* gaddr) {
    asm volatile("cp.async.cg.shared.global [%0], [%1], 16;" :: "r"(saddr), "l"(gaddr));
}
__device__ __forceinline__ void cp_commit() {
    asm volatile("cp.async.commit_group;");
}
template <int N>
__device__ __forceinline__ void cp_wait() {
    asm volatile("cp.async.wait_group %0;" :: "n"(N));
}
__device__ __forceinline__ void ldsm_x4(uint32_t* f, uint32_t addr) {
    asm volatile("ldmatrix.sync.aligned.m8n8.x4.shared.b16 {%0,%1,%2,%3}, [%4];"
                 : "=r"(f[0]), "=r"(f[1]), "=r"(f[2]), "=r"(f[3]) : "r"(addr));
}
__device__ __forceinline__ void ldsm_x4_t(uint32_t* f, uint32_t addr) {
    asm volatile("ldmatrix.sync.aligned.m8n8.x4.trans.shared.b16 {%0,%1,%2,%3}, [%4];"
                 : "=r"(f[0]), "=r"(f[1]), "=r"(f[2]), "=r"(f[3]) : "r"(addr));
}
__device__ __forceinline__ void mma_16816(float* c, const uint32_t* a, uint32_t b0, uint32_t b1) {
    asm volatile(
        "mma.sync.aligned.m16n8k16.row.col.f32.f16.f16.f32 "
        "{%0,%1,%2,%3}, {%4,%5,%6,%7}, {%8,%9}, {%0,%1,%2,%3};"
        : "+f"(c[0]), "+f"(c[1]), "+f"(c[2]), "+f"(c[3])
        : "r"(a[0]), "r"(a[1]), "r"(a[2]), "r"(a[3]), "r"(b0), "r"(b1));
}
__device__ __forceinline__ uint32_t csw8(uint32_t c, uint32_t row) {
    return (c & 0x8u) | ((c ^ (row & 7u)) & 0x7u);
}

// ---------------- fused prep + convA + convB ----------------
// Q/K fused columns (< 2304) are stored COLUMN-PERMUTED: logical head-dim d
// lives at physical p = 2*(d%64) + (d>=64). Q.K^T is invariant under a common
// permutation, so attention is unchanged; the QKV epilogue does RoPE in regs.
#define CONVB_BLKS (144 * 64)
__global__ void __launch_bounds__(256) conv_all_kernel(
    const float* __restrict__ X,
    const float* __restrict__ qw, const float* __restrict__ kw,
    const float* __restrict__ vw, const float* __restrict__ ow,
    const float* __restrict__ mask,
    const float* __restrict__ qb, const float* __restrict__ kb,
    const float* __restrict__ vb,
    __half* __restrict__ Ap, __half* __restrict__ Bqkv, __half* __restrict__ Bow,
    float* __restrict__ eff, float* __restrict__ bias)
{
    int blk = blockIdx.x;
    int tid = threadIdx.x;

    if (blk < 2048) {
        int g = blk * 256 + tid;
        int m = g >> 8;
        int kg = (g & 255) << 3;
        const float* xp = X + ((size_t)m << 11) + kg;
        float f[8];
        *(float4*)f       = *(const float4*)xp;
        *(float4*)(f + 4) = *(const float4*)(xp + 4);
        unsigned short h[8];
        #pragma unroll
        for (int i = 0; i < 8; i++) h[i] = __half_as_ushort(__float2half_rn(f[i]));
        *(uint4*)(Ap + (size_t)m * KP + kg) =
            make_uint4(pack2(h[0],h[1]), pack2(h[2],h[3]), pack2(h[4],h[5]), pack2(h[6],h[7]));
        return;
    }
    blk -= 2048;
    if (blk < CONVB_BLKS) {
        __shared__ float s[32][33];
        int bx = blk % 144, by = blk / 144;
        const float* W; __half* Bp; int N, noff, nx;
        if (bx < 64)      { W = qw; Bp = Bqkv; N = 2048; noff = 0;    nx = bx; }
        else if (bx < 72) { W = kw; Bp = Bqkv; N = 256;  noff = 2048; nx = bx - 64; }
        else if (bx < 80) { W = vw; Bp = Bqkv; N = 256;  noff = 2304; nx = bx - 72; }
        else              { W = ow; Bp = Bow;  N = 2048; noff = 0;    nx = bx - 80; }
        int n0 = nx << 5, k0 = by << 5;
        #pragma unroll
        for (int p = 0; p < 4; p++) {
            int e = tid + p * 256;
            int ki = e >> 5, ni = e & 31;
            s[ki][ni] = W[(size_t)(k0 + ki) * N + n0 + ni];
        }
        __syncthreads();
        if (tid < 128) {
            int ni = tid >> 2, kg = (tid & 3) << 3;
            unsigned short h[8];
            #pragma unroll
            for (int j = 0; j < 8; j++) h[j] = __half_as_ushort(__float2half_rn(s[kg + j][ni]));
            int g = noff + n0 + ni;
            int row;
            if (g < 2304 && Bp == Bqkv) {
                int d = g & 127;
                row = (g & ~127) | (2 * (d & 63) + (d >> 6));
            } else {
                row = g;
            }
            *(uint4*)(Bp + (size_t)row * KP + k0 + kg) =
                make_uint4(pack2(h[0],h[1]), pack2(h[2],h[3]), pack2(h[4],h[5]), pack2(h[6],h[7]));
        }
        return;
    }
    blk -= CONVB_BLKS;
    if (blk < 2) {
        float s = 0.f;
        for (int i = tid; i < S_; i += blockDim.x) s += mask[blk * S_ + i];
        #pragma unroll
        for (int off = 16; off; off >>= 1) s += __shfl_xor_sync(0xffffffffu, s, off);
        __shared__ float red[8];
        if ((tid & 31) == 0) red[tid >> 5] = s;
        __syncthreads();
        if (tid == 0) {
            float t = 0.f;
            for (int i = 0; i < 8; i++) t += red[i];
            eff[blk] = t;
        }
    } else {
        int i = (blk - 2) * 256 + tid;
        float v;
        if (i < 2048) v = qb[i];
        else if (i < 2304) v = kb[i - 2048];
        else if (i < 2560) v = vb[i - 2304];
        else return;
        int dst = i;
        if (i < 2304) {
            int d = i & 127;
            dst = (i & ~127) | (2 * (d & 63) + (d >> 6));
        }
        bias[dst] = v;
    }
}

// ================= O-proj GEMM (unchanged) =================
#define BKC 32
#define STAGE_B 16384
#define GEMM_SMEM 65536
#define KITERS (KP / BKC)

__device__ __forceinline__ void stage_load(uint32_t sbase, int stage,
                                           const __half* Ag, const __half* Bg,
                                           int k0, int lrow, int lchunk) {
    uint32_t sa = sbase + stage * STAGE_B;
    #pragma unroll
    for (int i = 0; i < 2; i++) {
        int row = lrow + i * 64;
        uint32_t sw = (uint32_t)((lchunk ^ ((row >> 1) & 3)) << 4);
        cp_async16(sa + row * 64 + sw,        Ag + (size_t)row * KP + k0 + lchunk * 8);
        cp_async16(sa + 8192 + row * 64 + sw, Bg + (size_t)row * KP + k0 + lchunk * 8);
    }
}

__global__ void __launch_bounds__(256, 2) gemm_mma_kernel(
    const __half* __restrict__ A, const __half* __restrict__ Bm,
    float* __restrict__ C, int Ntot)
{
    extern __shared__ char smc[];
    uint32_t sbase = smem_u32(smc);
    const int tid = threadIdx.x;
    const int mt = blockIdx.y, nt = blockIdx.x;
    const int warp = tid >> 5, lane = tid & 31;
    const int wm = warp >> 2, wn = warp & 3;
    const int lrow = tid >> 2;
    const int lchunk = tid & 3;
    const int arow = wm * 64 + ((lane >> 3) & 1) * 8 + (lane & 7);
    const int achi = (lane >> 4) & 1;
    const uint32_t asw = (uint32_t)((arow >> 1) & 3);
    const uint32_t abase = (uint32_t)(arow * 64);
    const int brow = wn * 32 + ((lane >> 4) & 1) * 8 + (lane & 7);
    const int bclo = (lane >> 3) & 1;
    const uint32_t bsw = (uint32_t)((brow >> 1) & 3);
    const uint32_t bbase = (uint32_t)(brow * 64);
    float acc[16][4];
    #pragma unroll
    for (int i = 0; i < 16; i++) { acc[i][0]=0.f; acc[i][1]=0.f; acc[i][2]=0.f; acc[i][3]=0.f; }

    const __half* Ag = A  + (size_t)(mt * 128) * KP;
    const __half* Bg = Bm + (size_t)(nt * 128) * KP;

    #pragma unroll
    for (int s = 0; s < 3; s++) { stage_load(sbase, s, Ag, Bg, s * BKC, lrow, lchunk); cp_commit(); }
    cp_wait<2>();
    __syncthreads();

    for (int kt = 0; kt < KITERS; kt++) {
        uint32_t sa = sbase + (kt & 3) * STAGE_B;
        uint32_t sb = sa + 8192;

        uint32_t af0[4][4], af1[4][4], bf00[4], bf01[4];
        #pragma unroll
        for (int m = 0; m < 4; m++)
            ldsm_x4(af0[m], sa + abase + m * 1024 + ((((uint32_t)achi) ^ asw) << 4));
        ldsm_x4(bf00, sb + bbase +        ((((uint32_t)bclo) ^ bsw) << 4));
        ldsm_x4(bf01, sb + bbase + 1024 + ((((uint32_t)bclo) ^ bsw) << 4));
        #pragma unroll
        for (int m = 0; m < 4; m++)
            ldsm_x4(af1[m], sa + abase + m * 1024 + ((((uint32_t)(2 + achi)) ^ asw) << 4));

        cp_wait<1>();
        __syncthreads();

        int nxt = kt + 3;
        if (nxt < KITERS) stage_load(sbase, nxt & 3, Ag, Bg, nxt * BKC, lrow, lchunk);
        cp_commit();

        #pragma unroll
        for (int m = 0; m < 4; m++) {
            mma_16816(acc[m * 4 + 0], af0[m], bf00[0], bf00[1]);
            mma_16816(acc[m * 4 + 1], af0[m], bf00[2], bf00[3]);
            mma_16816(acc[m * 4 + 2], af0[m], bf01[0], bf01[1]);
            mma_16816(acc[m * 4 + 3], af0[m], bf01[2], bf01[3]);
        }
        uint32_t bf10[4], bf11[4];
        ldsm_x4(bf10, sb + bbase +        ((((uint32_t)(2 + bclo)) ^ bsw) << 4));
        ldsm_x4(bf11, sb + bbase + 1024 + ((((uint32_t)(2 + bclo)) ^ bsw) << 4));
        #pragma unroll
        for (int m = 0; m < 4; m++) {
            mma_16816(acc[m * 4 + 0], af1[m], bf10[0], bf10[1]);
            mma_16816(acc[m * 4 + 1], af1[m], bf10[2], bf10[3]);
            mma_16816(acc[m * 4 + 2], af1[m], bf11[0], bf11[1]);
            mma_16816(acc[m * 4 + 3], af1[m], bf11[2], bf11[3]);
        }
    }

    #pragma unroll
    for (int n = 0; n < 4; n++) {
        int col = nt * 128 + wn * 32 + n * 8 + (lane & 3) * 2;
        #pragma unroll
        for (int m = 0; m < 4; m++) {
            int row = mt * 128 + wm * 64 + m * 16 + (lane >> 2);
            *(float2*)(C + (size_t)row * Ntot + col)       = make_float2(acc[m*4+n][0], acc[m*4+n][1]);
            *(float2*)(C + (size_t)(row + 8) * Ntot + col) = make_float2(acc[m*4+n][2], acc[m*4+n][3]);
        }
    }
}

// ================= fused QKV GEMM: register-RoPE epilogue =================
#define QSTAGE_B 12288
#define QKV_SMEM 49152

__device__ __forceinline__ void qstage_load(uint32_t sbase, int stage,
                                            const __half* Ag, const __half* Bg,
                                            int k0, int tid) {
    uint32_t sa = sbase + stage * QSTAGE_B;
    uint32_t sb = sa + 4096;
    int r = tid >> 2, c = tid & 3;
    uint32_t swa = (uint32_t)((c ^ ((r >> 1) & 3)) << 4);
    if (r < 64)
        cp_async16(sa + r * 64 + swa, Ag + (size_t)r * KP + k0 + c * 8);
    #pragma unroll
    for (int i = 0; i < 2; i++) {
        int rb = r + i * 64;
        uint32_t swb = (uint32_t)((c ^ ((rb >> 1) & 3)) << 4);
        cp_async16(sb + rb * 64 + swb, Bg + (size_t)rb * KP + k0 + c * 8);
    }
}

__global__ void __launch_bounds__(256, 2) gemm_qkv_fused(
    const __half* __restrict__ A, const __half* __restrict__ Bm,
    const float* __restrict__ bias,
    const float* __restrict__ cosb, const float* __restrict__ sinb,
    const float* __restrict__ mask,
    const float* __restrict__ q_gamma, const float* __restrict__ k_gamma,
    __half* __restrict__ Qpk, __half* __restrict__ Kpk, __half* __restrict__ Vpk)
{
    extern __shared__ char smc[];
    __shared__ float ssq[4][64];
    uint32_t sbase = smem_u32(smc);
    const int tid = threadIdx.x;
    const int nt = blockIdx.x, mt = blockIdx.y;
    const int warp = tid >> 5, lane = tid & 31;
    const int wm = warp >> 2, wn = warp & 3;

    const int arow = wm * 32 + ((lane >> 3) & 1) * 8 + (lane & 7);
    const int achi = (lane >> 4) & 1;
    const uint32_t asw = (uint32_t)((arow >> 1) & 3);
    const uint32_t abase = (uint32_t)(arow * 64);
    const int brow = wn * 32 + ((lane >> 4) & 1) * 8 + (lane & 7);
    const int bclo = (lane >> 3) & 1;
    const uint32_t bsw = (uint32_t)((brow >> 1) & 3);
    const uint32_t bbase = (uint32_t)(brow * 64);

    float acc[8][4];
    #pragma unroll
    for (int i = 0; i < 8; i++) { acc[i][0]=0.f; acc[i][1]=0.f; acc[i][2]=0.f; acc[i][3]=0.f; }

    const __half* Ag = A  + (size_t)(mt * 64) * KP;
    const __half* Bg = Bm + (size_t)(nt * 128) * KP;

    #pragma unroll
    for (int s = 0; s < 3; s++) { qstage_load(sbase, s, Ag, Bg, s * BKC, tid); cp_commit(); }
    cp_wait<2>();
    __syncthreads();

    for (int kt = 0; kt < KITERS; kt++) {
        uint32_t sa = sbase + (kt & 3) * QSTAGE_B;
        uint32_t sb = sa + 4096;

        uint32_t af0[2][4], af1[2][4], bf00[4], bf01[4];
        #pragma unroll
        for (int m = 0; m < 2; m++)
            ldsm_x4(af0[m], sa + abase + m * 1024 + ((((uint32_t)achi) ^ asw) << 4));
        ldsm_x4(bf00, sb + bbase +        ((((uint32_t)bclo) ^ bsw) << 4));
        ldsm_x4(bf01, sb + bbase + 1024 + ((((uint32_t)bclo) ^ bsw) << 4));
        #pragma unroll
        for (int m = 0; m < 2; m++)
            ldsm_x4(af1[m], sa + abase + m * 1024 + ((((uint32_t)(2 + achi)) ^ asw) << 4));

        cp_wait<1>();
        __syncthreads();

        int nxt = kt + 3;
        if (nxt < KITERS) qstage_load(sbase, nxt & 3, Ag, Bg, nxt * BKC, tid);
        cp_commit();

        #pragma unroll
        for (int m = 0; m < 2; m++) {
            mma_16816(acc[m * 4 + 0], af0[m], bf00[0], bf00[1]);
            mma_16816(acc[m * 4 + 1], af0[m], bf00[2], bf00[3]);
            mma_16816(acc[m * 4 + 2], af0[m], bf01[0], bf01[1]);
            mma_16816(acc[m * 4 + 3], af0[m], bf01[2], bf01[3]);
        }
        uint32_t bf10[4], bf11[4];
        ldsm_x4(bf10, sb + bbase +        ((((uint32_t)(2 + bclo)) ^ bsw) << 4));
        ldsm_x4(bf11, sb + bbase + 1024 + ((((uint32_t)(2 + bclo)) ^ bsw) << 4));
        #pragma unroll
        for (int m = 0; m < 2; m++) {
            mma_16816(acc[m * 4 + 0], af1[m], bf10[0], bf10[1]);
            mma_16816(acc[m * 4 + 1], af1[m], bf10[2], bf10[3]);
            mma_16816(acc[m * 4 + 2], af1[m], bf11[0], bf11[1]);
            mma_16816(acc[m * 4 + 3], af1[m], bf11[2], bf11[3]);
        }
    }

    cp_wait<0>();

    // bias add (bias is pre-permuted for Q/K blocks)
    #pragma unroll
    for (int n = 0; n < 4; n++) {
        int col = wn * 32 + n * 8 + (lane & 3) * 2;
        float b0 = bias[nt * 128 + col];
        float b1 = bias[nt * 128 + col + 1];
        #pragma unroll
        for (int m = 0; m < 2; m++) {
            acc[m*4+n][0] += b0; acc[m*4+n][1] += b1;
            acc[m*4+n][2] += b0; acc[m*4+n][3] += b1;
        }
    }

    if (nt >= 18) {
        // ---- V (identity layout) ----
        int kh = nt - 18;
        #pragma unroll
        for (int m = 0; m < 2; m++) {
            int t0 = mt * 64 + wm * 32 + m * 16 + (lane >> 2);
            int b0g = t0 >> 10, s0g = t0 & 1023;
            float mv0 = mask[t0], mv1 = mask[t0 + 8];
            __half* vp0 = Vpk + ((size_t)(b0g * NKV_ + kh) * S_ + s0g) * 128;
            __half* vp1 = vp0 + 8 * 128;
            #pragma unroll
            for (int n = 0; n < 4; n++) {
                int col = wn * 32 + n * 8 + (lane & 3) * 2;
                *(__half2*)(vp0 + col) = __floats2half2_rn(acc[m*4+n][0] * mv0, acc[m*4+n][1] * mv0);
                *(__half2*)(vp1 + col) = __floats2half2_rn(acc[m*4+n][2] * mv1, acc[m*4+n][3] * mv1);
            }
        }
        return;
    }

    // ---- Q or K: RMSNorm (ssq reduce) + register RoPE via permuted layout ----
    const bool isQ = (nt < 16);
    const float* gamma = isQ ? q_gamma : k_gamma;
    int hh = isQ ? nt : (nt - 16);

    #pragma unroll
    for (int m = 0; m < 2; m++) {
        float a0 = 0.f, a1 = 0.f;
        #pragma unroll
        for (int n = 0; n < 4; n++) {
            a0 += acc[m*4+n][0]*acc[m*4+n][0] + acc[m*4+n][1]*acc[m*4+n][1];
            a1 += acc[m*4+n][2]*acc[m*4+n][2] + acc[m*4+n][3]*acc[m*4+n][3];
        }
        a0 += __shfl_xor_sync(0xffffffffu, a0, 1);
        a0 += __shfl_xor_sync(0xffffffffu, a0, 2);
        a1 += __shfl_xor_sync(0xffffffffu, a1, 1);
        a1 += __shfl_xor_sync(0xffffffffu, a1, 2);
        if ((lane & 3) == 0) {
            int r0 = wm * 32 + m * 16 + (lane >> 2);
            ssq[wn][r0]     = a0;
            ssq[wn][r0 + 8] = a1;
        }
    }
    __syncthreads();

    const int dbase = wn * 16 + (lane & 3);   // logical d for fragment element 0
    const int pbase = wn * 32 + (lane & 3) * 2;

    #pragma unroll
    for (int m = 0; m < 2; m++) {
        int r0 = wm * 32 + m * 16 + (lane >> 2);
        int r1 = r0 + 8;
        float rms0 = rsqrtf((ssq[0][r0]+ssq[1][r0]+ssq[2][r0]+ssq[3][r0]) * (1.0f / HD_) + 1e-6f);
        float rms1 = rsqrtf((ssq[0][r1]+ssq[1][r1]+ssq[2][r1]+ssq[3][r1]) * (1.0f / HD_) + 1e-6f);
        int t_0 = mt * 64 + r0;
        int t_1 = t_0 + 8;
        int b0g = t_0 >> 10, s0g = t_0 & 1023;
        int b1g = t_1 >> 10, s1g = t_1 & 1023;
        float mv0 = 1.f, mv1 = 1.f;
        __half *out0, *out1;
        if (isQ) {
            out0 = Qpk + ((size_t)(b0g * NH_ + hh) * S_ + s0g) * 128;
            out1 = Qpk + ((size_t)(b1g * NH_ + hh) * S_ + s1g) * 128;
        } else {
            mv0 = mask[t_0]; mv1 = mask[t_1];
            out0 = Kpk + ((size_t)(b0g * NKV_ + hh) * S_ + s0g) * 128;
            out1 = Kpk + ((size_t)(b1g * NKV_ + hh) * S_ + s1g) * 128;
        }
        #pragma unroll
        for (int n = 0; n < 4; n++) {
            int d = dbase + n * 4;
            int sec = (d < 16) ? 0 : (d < 40) ? 1 : 2;
            float g0 = gamma[d], g1 = gamma[d + 64];
            size_t ci0 = (((size_t)sec * B_ + b0g) * S_ + s0g) * HD_ + d;
            size_t ci1 = (((size_t)sec * B_ + b1g) * S_ + s1g) * HD_ + d;
            int idx = m * 4 + n;
            int p = pbase + n * 8;

            float nvA = acc[idx][0] * rms0 * g0;    // logical d, row r0
            float nvB = acc[idx][1] * rms0 * g1;    // logical d+64, row r0
            float o0 = nvA * cosb[ci0]      - nvB * sinb[ci0];
            float o1 = nvB * cosb[ci0 + 64] + nvA * sinb[ci0 + 64];
            *(__half2*)(out0 + p) = __floats2half2_rn(o0 * mv0, o1 * mv0);

            nvA = acc[idx][2] * rms1 * g0;          // row r1
            nvB = acc[idx][3] * rms1 * g1;
            o0 = nvA * cosb[ci1]      - nvB * sinb[ci1];
            o1 = nvB * cosb[ci1 + 64] + nvA * sinb[ci1 + 64];
            *(__half2*)(out1 + p) = __floats2half2_rn(o0 * mv1, o1 * mv1);
        }
    }
}

// ---------------- tensor-core flash attention (permutation-invariant, unchanged) ----------------
#define ATTN_SMEM 81920

__global__ void __launch_bounds__(128, 2) attn_tc_kernel(
    const __half* __restrict__ Qpk, const __half* __restrict__ Kpk,
    const __half* __restrict__ Vpk, const float* __restrict__ eff,
    __half* __restrict__ Apk)
{
    extern __shared__ char smc[];
    uint32_t sbase = smem_u32(smc);

    int bid = blockIdx.x;
    int qt = 15 - (bid >> 5);
    int rem = bid & 31;
    int h = rem >> 1, b = rem & 1;
    int kvh = h / G_;
    int tid = threadIdx.x, warp = tid >> 5, lane = tid & 31;

    const __half* Qg = Qpk + ((size_t)(b * NH_ + h) * S_ + qt * 64) * 128;
    const __half* Kg = Kpk + ((size_t)(b * NKV_ + kvh) * S_) * 128;
    const __half* Vg = Vpk + ((size_t)(b * NKV_ + kvh) * S_) * 128;

    #pragma unroll
    for (int it = 0; it < 8; it++) {
        int idx = it * 128 + tid;
        int r = idx >> 4, c = idx & 15;
        cp_async16(sbase + r * 256 + csw8(c, r) * 16, Qg + (size_t)r * 128 + c * 8);
    }
    cp_commit();
    cp_wait<0>();
    __syncthreads();

    uint32_t qh[8][4];
    {
        int row = warp * 16 + ((lane >> 3) & 1) * 8 + (lane & 7);
        uint32_t roff = sbase + row * 256;
        uint32_t r7 = row & 7;
        int chi = (lane >> 4) & 1;
        #pragma unroll
        for (int j = 0; j < 8; j++) {
            uint32_t ch = 2 * j + chi;
            ldsm_x4(qh[j], roff + ((ch & 8u) | ((ch ^ r7) & 7u)) * 16);
        }
    }

    int ntiles = qt + 1;
    int eff_i = (int)(eff[b] + 0.5f);

    #pragma unroll
    for (int pt = 0; pt < 2; pt++) {
        if (pt < ntiles) {
            #pragma unroll
            for (int it = 0; it < 8; it++) {
                int idx = it * 128 + tid;
                int r = idx >> 4, c = idx & 15;
                uint32_t ds = 16384u + (uint32_t)pt * 32768 + r * 256 + csw8(c, r) * 16;
                size_t go = (size_t)(pt * 64 + r) * 128 + c * 8;
                cp_async16(sbase + ds,         Kg + go);
                cp_async16(sbase + ds + 16384, Vg + go);
            }
        }
        cp_commit();
    }

    float m0 = -1e30f, m1 = -1e30f, ls0 = 0.f, ls1 = 0.f;
    float o[16][4];
    #pragma unroll
    for (int i = 0; i < 16; i++) { o[i][0] = o[i][1] = o[i][2] = o[i][3] = 0.f; }

    const float scale = 0.08838834764831845f;
    int row0 = qt * 64 + warp * 16 + (lane >> 2);
    int colb = (lane & 3) * 2;
    int krbase = ((lane >> 4) & 1) * 8 + (lane & 7);
    int kchi = (lane >> 3) & 1;
    int vrbase = ((lane >> 3) & 1) * 8 + (lane & 7);
    int vchi = (lane >> 4) & 1;

    for (int kt = 0; kt < ntiles; kt++) {
        cp_wait<1>();
        __syncthreads();
        uint32_t sk = sbase + 16384u + (uint32_t)(kt & 1) * 32768;
        uint32_t sv = sk + 16384;

        float s[8][4];
        #pragma unroll
        for (int i = 0; i < 8; i++) { s[i][0] = s[i][1] = s[i][2] = s[i][3] = 0.f; }

        #pragma unroll
        for (int nbp = 0; nbp < 4; nbp++) {
            int krow = nbp * 16 + krbase;
            uint32_t kroff = sk + krow * 256;
            uint32_t kr7 = krow & 7;
            #pragma unroll
            for (int j = 0; j < 8; j++) {
                uint32_t ch = 2 * j + kchi;
                uint32_t kf[4];
                ldsm_x4(kf, kroff + ((ch & 8u) | ((ch ^ kr7) & 7u)) * 16);
                mma_16816(s[2*nbp],   qh[j], kf[0], kf[1]);
                mma_16816(s[2*nbp+1], qh[j], kf[2], kf[3]);
            }
        }

        float mx0 = -1e30f, mx1 = -1e30f;
        #pragma unroll
        for (int nb = 0; nb < 8; nb++) {
            int c0 = kt * 64 + nb * 8 + colb;
            #pragma unroll
            for (int e = 0; e < 2; e++) {
                int cc = c0 + e;
                float v0 = (cc <= row0     && cc < eff_i) ? s[nb][e]   * scale : -1e9f;
                float v1 = (cc <= row0 + 8 && cc < eff_i) ? s[nb][2+e] * scale : -1e9f;
                s[nb][e] = v0; s[nb][2+e] = v1;
                mx0 = fmaxf(mx0, v0); mx1 = fmaxf(mx1, v1);
            }
        }
        mx0 = fmaxf(mx0, __shfl_xor_sync(0xffffffffu, mx0, 1));
        mx0 = fmaxf(mx0, __shfl_xor_sync(0xffffffffu, mx0, 2));
        mx1 = fmaxf(mx1, __shfl_xor_sync(0xffffffffu, mx1, 1));
        mx1 = fmaxf(mx1, __shfl_xor_sync(0xffffffffu, mx1, 2));
        float m0n = fmaxf(m0, mx0), m1n = fmaxf(m1, mx1);
        float cr0 = __expf(m0 - m0n), cr1 = __expf(m1 - m1n);
        float sum0 = 0.f, sum1 = 0.f;
        #pragma unroll
        for (int nb = 0; nb < 8; nb++) {
            #pragma unroll
            for (int e = 0; e < 2; e++) {
                float p0 = __expf(s[nb][e]   - m0n);
                float p1 = __expf(s[nb][2+e] - m1n);
                s[nb][e] = p0; s[nb][2+e] = p1;
                sum0 += p0; sum1 += p1;
            }
        }
        sum0 += __shfl_xor_sync(0xffffffffu, sum0, 1);
        sum0 += __shfl_xor_sync(0xffffffffu, sum0, 2);
        sum1 += __shfl_xor_sync(0xffffffffu, sum1, 1);
        sum1 += __shfl_xor_sync(0xffffffffu, sum1, 2);
        ls0 = ls0 * cr0 + sum0; m0 = m0n;
        ls1 = ls1 * cr1 + sum1; m1 = m1n;
        #pragma unroll
        for (int i = 0; i < 16; i++) {
            o[i][0] *= cr0; o[i][1] *= cr0;
            o[i][2] *= cr1; o[i][3] *= cr1;
        }

        uint32_t ph[4][4];
        #pragma unroll
        for (int j2 = 0; j2 < 4; j2++) {
            #pragma unroll
            for (int q = 0; q < 4; q++) {
                int nb = 2 * j2 + (q >> 1);
                int e  = (q & 1) * 2;
                unsigned short ha = __half_as_ushort(__float2half_rn(s[nb][e]));
                unsigned short hb = __half_as_ushort(__float2half_rn(s[nb][e + 1]));
                ph[j2][(q >> 1) * 2 + (q & 1)] = pack2(ha, hb);
            }
        }

        #pragma unroll
        for (int j2 = 0; j2 < 4; j2++) {
            int vrow = j2 * 16 + vrbase;
            uint32_t vroff = sv + vrow * 256;
            uint32_t vr7 = vrow & 7;
            #pragma unroll
            for (int nbp = 0; nbp < 8; nbp++) {
                uint32_t ch = 2 * nbp + vchi;
                uint32_t vf[4];
                ldsm_x4_t(vf, vroff + ((ch & 8u) | ((ch ^ vr7) & 7u)) * 16);
                mma_16816(o[2*nbp],   ph[j2], vf[0], vf[1]);
                mma_16816(o[2*nbp+1], ph[j2], vf[2], vf[3]);
            }
        }

        __syncthreads();
        int nxt = kt + 2;
        if (nxt < ntiles) {
            #pragma unroll
            for (int it = 0; it < 8; it++) {
                int idx = it * 128 + tid;
                int r = idx >> 4, c = idx & 15;
                uint32_t ds = 16384u + (uint32_t)(kt & 1) * 32768 + r * 256 + csw8(c, r) * 16;
                size_t go = (size_t)(nxt * 64 + r) * 128 + c * 8;
                cp_async16(sbase + ds,         Kg + go);
                cp_async16(sbase + ds + 16384, Vg + go);
            }
        }
        cp_commit();
    }

    float inv0 = 1.0f / ls0, inv1 = 1.0f / ls1;
    int t0 = b * S_ + qt * 64 + warp * 16 + (lane >> 2);
    size_t r0b = (size_t)t0 * KP;
    size_t r1b = (size_t)(t0 + 8) * KP;
    #pragma unroll
    for (int db = 0; db < 16; db++) {
        int c = h * 128 + db * 8 + colb;
        __half h0 = __float2half_rn(o[db][0] * inv0);
        __half h1 = __float2half_rn(o[db][1] * inv0);
        *(uint32_t*)(Apk + r0b + c) = pack2(__half_as_ushort(h0), __half_as_ushort(h1));
        h0 = __float2half_rn(o[db][2] * inv1);
        h1 = __float2half_rn(o[db][3] * inv1);
        *(uint32_t*)(Apk + r1b + c) = pack2(__half_as_ushort(h0), __half_as_ushort(h1));
    }
}

// ---------------- launcher ----------------
extern "C" void kernel_launch(void* const* d_in, const int* in_sizes, int n_in,
                              void* d_out, int out_size)
{
    const float* x       = (const float*)d_in[0];
    const float* cosb    = (const float*)d_in[1];
    const float* sinb    = (const float*)d_in[2];
    const float* mask    = (const float*)d_in[3];
    const float* q_w     = (const float*)d_in[4];
    const float* q_b     = (const float*)d_in[5];
    const float* k_w     = (const float*)d_in[6];
    const float* k_b     = (const float*)d_in[7];
    const float* v_w     = (const float*)d_in[8];
    const float* v_b     = (const float*)d_in[9];
    const float* q_gamma = (const float*)d_in[10];
    const float* k_gamma = (const float*)d_in[11];
    const float* o_w     = (const float*)d_in[12];
    float* out = (float*)d_out;

    float* scratch = nullptr;
    cudaGetSymbolAddress((void**)&scratch, g_scratch);
    float* geff = scratch + OFF_EFF;
    float* bias = scratch + OFF_BIAS;
    __half* Apack = (__half*)(scratch + OFF_APK);
    __half* Bqkv  = (__half*)(scratch + OFF_BQKV);
    __half* Bow   = (__half*)(scratch + OFF_BOW);
    __half* Qpk   = (__half*)(scratch + OFF_QPK);
    __half* Kpk   = (__half*)(scratch + OFF_KPK);
    __half* Vpk   = (__half*)(scratch + OFF_VPK);

    cudaFuncSetAttribute(gemm_mma_kernel, cudaFuncAttributeMaxDynamicSharedMemorySize, GEMM_SMEM);
    cudaFuncSetAttribute(gemm_qkv_fused,  cudaFuncAttributeMaxDynamicSharedMemorySize, QKV_SMEM);
    cudaFuncSetAttribute(attn_tc_kernel,  cudaFuncAttributeMaxDynamicSharedMemorySize, ATTN_SMEM);

    conv_all_kernel<<<2048 + CONVB_BLKS + 12, 256>>>(
        x, q_w, k_w, v_w, o_w, mask, q_b, k_b, v_b,
        Apack, Bqkv, Bow, geff, bias);
    gemm_qkv_fused<<<dim3(NQKV / 128, 32), 256, QKV_SMEM>>>(
        Apack, Bqkv, bias, cosb, sinb, mask, q_gamma, k_gamma, Qpk, Kpk, Vpk);
    attn_tc_kernel<<<512, 128, ATTN_SMEM>>>(Qpk, Kpk, Vpk, geff, Apack);
    gemm_mma_kernel<<<dim3(16, 16), 256, GEMM_SMEM>>>(Apack, Bow, out, 2048);
}

// round 15
// speedup vs baseline: 1.0071x; 1.0071x over previous
#include <cuda_runtime.h>
#include <cuda_fp16.h>
#include <math.h>
#include <stdint.h>

#define B_   2
#define S_   1024
#define HID_ 2048
#define NH_  16
#define NKV_ 2
#define HD_  128
#define G_   (NH_/NKV_)
#define TOK  (B_*S_)

#define KP   2048
#define NQKV 2560

// ---------------- scratch ----------------
#define OFF_EFF  0
#define OFF_BIAS 4
#define OFF_APK  2564
#define OFF_BQKV 2099716
#define OFF_BOW  4721156
#define OFF_QPK  6818308
#define OFF_KPK  8915460
#define OFF_VPK  9177604
#define SCRATCH_F 9439748
__device__ __align__(256) float g_scratch[SCRATCH_F];

// ---------------- helpers ----------------
__device__ __forceinline__ uint32_t smem_u32(const void* p) {
    uint32_t a;
    asm("{ .reg .u64 t; cvta.to.shared.u64 t, %1; cvt.u32.u64 %0, t; }" : "=r"(a) : "l"(p));
    return a;
}
__device__ __forceinline__ uint32_t pack2(unsigned short a, unsigned short b) {
    return (uint32_t)a | ((uint32_t)b << 16);
}
__device__ __forceinline__ void cp_async16(uint32_t saddr, const void* gaddr) {
    asm volatile("cp.async.cg.shared.global [%0], [%1], 16;" :: "r"(saddr), "l"(gaddr));
}
__device__ __forceinline__ void cp_commit() {
    asm volatile("cp.async.commit_group;");
}
template <int N>
__device__ __forceinline__ void cp_wait() {
    asm volatile("cp.async.wait_group %0;" :: "n"(N));
}
__device__ __forceinline__ void ldsm_x4(uint32_t* f, uint32_t addr) {
    asm volatile("ldmatrix.sync.aligned.m8n8.x4.shared.b16 {%0,%1,%2,%3}, [%4];"
                 : "=r"(f[0]), "=r"(f[1]), "=r"(f[2]), "=r"(f[3]) : "r"(addr));
}
__device__ __forceinline__ void ldsm_x4_t(uint32_t* f, uint32_t addr) {
    asm volatile("ldmatrix.sync.aligned.m8n8.x4.trans.shared.b16 {%0,%1,%2,%3}, [%4];"
                 : "=r"(f[0]), "=r"(f[1]), "=r"(f[2]), "=r"(f[3]) : "r"(addr));
}
__device__ __forceinline__ void mma_16816(float* c, const uint32_t* a, uint32_t b0, uint32_t b1) {
    asm volatile(
        "mma.sync.aligned.m16n8k16.row.col.f32.f16.f16.f32 "
        "{%0,%1,%2,%3}, {%4,%5,%6,%7}, {%8,%9}, {%0,%1,%2,%3};"
        : "+f"(c[0]), "+f"(c[1]), "+f"(c[2]), "+f"(c[3])
        : "r"(a[0]), "r"(a[1]), "r"(a[2]), "r"(a[3]), "r"(b0), "r"(b1));
}
__device__ __forceinline__ uint32_t csw8(uint32_t c, uint32_t row) {
    return (c & 0x8u) | ((c ^ (row & 7u)) & 0x7u);
}

// ---------------- fused prep + convA + convB(Q/K/V only) ----------------
// Q/K fused columns (< 2304) column-permuted: logical d -> p = 2*(d%64) + (d>=64).
#define CONVB_BLKS (80 * 64)
__global__ void __launch_bounds__(256) conv_all_kernel(
    const float* __restrict__ X,
    const float* __restrict__ qw, const float* __restrict__ kw,
    const float* __restrict__ vw,
    const float* __restrict__ mask,
    const float* __restrict__ qb, const float* __restrict__ kb,
    const float* __restrict__ vb,
    __half* __restrict__ Ap, __half* __restrict__ Bqkv,
    float* __restrict__ eff, float* __restrict__ bias)
{
    int blk = blockIdx.x;
    int tid = threadIdx.x;

    if (blk < 2048) {
        int g = blk * 256 + tid;
        int m = g >> 8;
        int kg = (g & 255) << 3;
        const float* xp = X + ((size_t)m << 11) + kg;
        float f[8];
        *(float4*)f       = *(const float4*)xp;
        *(float4*)(f + 4) = *(const float4*)(xp + 4);
        unsigned short h[8];
        #pragma unroll
        for (int i = 0; i < 8; i++) h[i] = __half_as_ushort(__float2half_rn(f[i]));
        *(uint4*)(Ap + (size_t)m * KP + kg) =
            make_uint4(pack2(h[0],h[1]), pack2(h[2],h[3]), pack2(h[4],h[5]), pack2(h[6],h[7]));
        return;
    }
    blk -= 2048;
    if (blk < CONVB_BLKS) {
        __shared__ float s[32][33];
        int bx = blk % 80, by = blk / 80;
        const float* W; int N, noff, nx;
        if (bx < 64)      { W = qw; N = 2048; noff = 0;    nx = bx; }
        else if (bx < 72) { W = kw; N = 256;  noff = 2048; nx = bx - 64; }
        else              { W = vw; N = 256;  noff = 2304; nx = bx - 72; }
        int n0 = nx << 5, k0 = by << 5;
        #pragma unroll
        for (int p = 0; p < 4; p++) {
            int e = tid + p * 256;
            int ki = e >> 5, ni = e & 31;
            s[ki][ni] = W[(size_t)(k0 + ki) * N + n0 + ni];
        }
        __syncthreads();
        if (tid < 128) {
            int ni = tid >> 2, kg = (tid & 3) << 3;
            unsigned short h[8];
            #pragma unroll
            for (int j = 0; j < 8; j++) h[j] = __half_as_ushort(__float2half_rn(s[kg + j][ni]));
            int g = noff + n0 + ni;
            int row = g;
            if (g < 2304) {
                int d = g & 127;
                row = (g & ~127) | (2 * (d & 63) + (d >> 6));
            }
            *(uint4*)(Bqkv + (size_t)row * KP + k0 + kg) =
                make_uint4(pack2(h[0],h[1]), pack2(h[2],h[3]), pack2(h[4],h[5]), pack2(h[6],h[7]));
        }
        return;
    }
    blk -= CONVB_BLKS;
    if (blk < 2) {
        float s = 0.f;
        for (int i = tid; i < S_; i += blockDim.x) s += mask[blk * S_ + i];
        #pragma unroll
        for (int off = 16; off; off >>= 1) s += __shfl_xor_sync(0xffffffffu, s, off);
        __shared__ float red[8];
        if ((tid & 31) == 0) red[tid >> 5] = s;
        __syncthreads();
        if (tid == 0) {
            float t = 0.f;
            for (int i = 0; i < 8; i++) t += red[i];
            eff[blk] = t;
        }
    } else {
        int i = (blk - 2) * 256 + tid;
        float v;
        if (i < 2048) v = qb[i];
        else if (i < 2304) v = kb[i - 2048];
        else if (i < 2560) v = vb[i - 2304];
        else return;
        int dst = i;
        if (i < 2304) {
            int d = i & 127;
            dst = (i & ~127) | (2 * (d & 63) + (d >> 6));
        }
        bias[dst] = v;
    }
}

// ================= O-proj GEMM (unchanged) =================
#define BKC 32
#define STAGE_B 16384
#define GEMM_SMEM 65536
#define KITERS (KP / BKC)

__device__ __forceinline__ void stage_load(uint32_t sbase, int stage,
                                           const __half* Ag, const __half* Bg,
                                           int k0, int lrow, int lchunk) {
    uint32_t sa = sbase + stage * STAGE_B;
    #pragma unroll
    for (int i = 0; i < 2; i++) {
        int row = lrow + i * 64;
        uint32_t sw = (uint32_t)((lchunk ^ ((row >> 1) & 3)) << 4);
        cp_async16(sa + row * 64 + sw,        Ag + (size_t)row * KP + k0 + lchunk * 8);
        cp_async16(sa + 8192 + row * 64 + sw, Bg + (size_t)row * KP + k0 + lchunk * 8);
    }
}

__global__ void __launch_bounds__(256, 2) gemm_mma_kernel(
    const __half* __restrict__ A, const __half* __restrict__ Bm,
    float* __restrict__ C, int Ntot)
{
    extern __shared__ char smc[];
    uint32_t sbase = smem_u32(smc);
    const int tid = threadIdx.x;
    const int mt = blockIdx.y, nt = blockIdx.x;
    const int warp = tid >> 5, lane = tid & 31;
    const int wm = warp >> 2, wn = warp & 3;
    const int lrow = tid >> 2;
    const int lchunk = tid & 3;
    const int arow = wm * 64 + ((lane >> 3) & 1) * 8 + (lane & 7);
    const int achi = (lane >> 4) & 1;
    const uint32_t asw = (uint32_t)((arow >> 1) & 3);
    const uint32_t abase = (uint32_t)(arow * 64);
    const int brow = wn * 32 + ((lane >> 4) & 1) * 8 + (lane & 7);
    const int bclo = (lane >> 3) & 1;
    const uint32_t bsw = (uint32_t)((brow >> 1) & 3);
    const uint32_t bbase = (uint32_t)(brow * 64);
    float acc[16][4];
    #pragma unroll
    for (int i = 0; i < 16; i++) { acc[i][0]=0.f; acc[i][1]=0.f; acc[i][2]=0.f; acc[i][3]=0.f; }

    const __half* Ag = A  + (size_t)(mt * 128) * KP;
    const __half* Bg = Bm + (size_t)(nt * 128) * KP;

    #pragma unroll
    for (int s = 0; s < 3; s++) { stage_load(sbase, s, Ag, Bg, s * BKC, lrow, lchunk); cp_commit(); }
    cp_wait<2>();
    __syncthreads();

    for (int kt = 0; kt < KITERS; kt++) {
        uint32_t sa = sbase + (kt & 3) * STAGE_B;
        uint32_t sb = sa + 8192;

        uint32_t af0[4][4], af1[4][4], bf00[4], bf01[4];
        #pragma unroll
        for (int m = 0; m < 4; m++)
            ldsm_x4(af0[m], sa + abase + m * 1024 + ((((uint32_t)achi) ^ asw) << 4));
        ldsm_x4(bf00, sb + bbase +        ((((uint32_t)bclo) ^ bsw) << 4));
        ldsm_x4(bf01, sb + bbase + 1024 + ((((uint32_t)bclo) ^ bsw) << 4));
        #pragma unroll
        for (int m = 0; m < 4; m++)
            ldsm_x4(af1[m], sa + abase + m * 1024 + ((((uint32_t)(2 + achi)) ^ asw) << 4));

        cp_wait<1>();
        __syncthreads();

        int nxt = kt + 3;
        if (nxt < KITERS) stage_load(sbase, nxt & 3, Ag, Bg, nxt * BKC, lrow, lchunk);
        cp_commit();

        #pragma unroll
        for (int m = 0; m < 4; m++) {
            mma_16816(acc[m * 4 + 0], af0[m], bf00[0], bf00[1]);
            mma_16816(acc[m * 4 + 1], af0[m], bf00[2], bf00[3]);
            mma_16816(acc[m * 4 + 2], af0[m], bf01[0], bf01[1]);
            mma_16816(acc[m * 4 + 3], af0[m], bf01[2], bf01[3]);
        }
        uint32_t bf10[4], bf11[4];
        ldsm_x4(bf10, sb + bbase +        ((((uint32_t)(2 + bclo)) ^ bsw) << 4));
        ldsm_x4(bf11, sb + bbase + 1024 + ((((uint32_t)(2 + bclo)) ^ bsw) << 4));
        #pragma unroll
        for (int m = 0; m < 4; m++) {
            mma_16816(acc[m * 4 + 0], af1[m], bf10[0], bf10[1]);
            mma_16816(acc[m * 4 + 1], af1[m], bf10[2], bf10[3]);
            mma_16816(acc[m * 4 + 2], af1[m], bf11[0], bf11[1]);
            mma_16816(acc[m * 4 + 3], af1[m], bf11[2], bf11[3]);
        }
    }

    #pragma unroll
    for (int n = 0; n < 4; n++) {
        int col = nt * 128 + wn * 32 + n * 8 + (lane & 3) * 2;
        #pragma unroll
        for (int m = 0; m < 4; m++) {
            int row = mt * 128 + wm * 64 + m * 16 + (lane >> 2);
            *(float2*)(C + (size_t)row * Ntot + col)       = make_float2(acc[m*4+n][0], acc[m*4+n][1]);
            *(float2*)(C + (size_t)(row + 8) * Ntot + col) = make_float2(acc[m*4+n][2], acc[m*4+n][3]);
        }
    }
}

// ================= fused QKV GEMM + overlapped Bow pack =================
// 1D grid: blocks [0,640) = GEMM tiles (nt = blk%20, mt = blk/20);
// blocks [640,704) = Bow conversion units (32 N-rows x full K each),
// overlapping memory-bound weight packing under the tensor-bound GEMM.
#define QSTAGE_B 12288
#define QKV_SMEM 49152
#define QKV_GEMM_BLKS 640
#define OW_UNITS 64

__device__ __forceinline__ void qstage_load(uint32_t sbase, int stage,
                                            const __half* Ag, const __half* Bg,
                                            int k0, int tid) {
    uint32_t sa = sbase + stage * QSTAGE_B;
    uint32_t sb = sa + 4096;
    int r = tid >> 2, c = tid & 3;
    uint32_t swa = (uint32_t)((c ^ ((r >> 1) & 3)) << 4);
    if (r < 64)
        cp_async16(sa + r * 64 + swa, Ag + (size_t)r * KP + k0 + c * 8);
    #pragma unroll
    for (int i = 0; i < 2; i++) {
        int rb = r + i * 64;
        uint32_t swb = (uint32_t)((c ^ ((rb >> 1) & 3)) << 4);
        cp_async16(sb + rb * 64 + swb, Bg + (size_t)rb * KP + k0 + c * 8);
    }
}

__global__ void __launch_bounds__(256, 2) gemm_qkv_fused(
    const __half* __restrict__ A, const __half* __restrict__ Bm,
    const float* __restrict__ bias,
    const float* __restrict__ cosb, const float* __restrict__ sinb,
    const float* __restrict__ mask,
    const float* __restrict__ q_gamma, const float* __restrict__ k_gamma,
    const float* __restrict__ ow, __half* __restrict__ Bow,
    __half* __restrict__ Qpk, __half* __restrict__ Kpk, __half* __restrict__ Vpk)
{
    extern __shared__ char smc[];
    __shared__ float ssq[4][64];
    __shared__ float ts[32][33];
    const int tid = threadIdx.x;
    int blk = blockIdx.x;

    if (blk >= QKV_GEMM_BLKS) {
        // ---- overlapped Bow pack: unit = 32 N-rows x 2048 K ----
        int n0 = (blk - QKV_GEMM_BLKS) << 5;
        for (int by = 0; by < 64; by++) {
            int k0 = by << 5;
            #pragma unroll
            for (int p = 0; p < 4; p++) {
                int e = tid + p * 256;
                int ki = e >> 5, ni = e & 31;
                ts[ki][ni] = ow[(size_t)(k0 + ki) * 2048 + n0 + ni];
            }
            __syncthreads();
            if (tid < 128) {
                int ni = tid >> 2, kg = (tid & 3) << 3;
                unsigned short h[8];
                #pragma unroll
                for (int j = 0; j < 8; j++) h[j] = __half_as_ushort(__float2half_rn(ts[kg + j][ni]));
                *(uint4*)(Bow + (size_t)(n0 + ni) * KP + k0 + kg) =
                    make_uint4(pack2(h[0],h[1]), pack2(h[2],h[3]), pack2(h[4],h[5]), pack2(h[6],h[7]));
            }
            __syncthreads();
        }
        return;
    }

    uint32_t sbase = smem_u32(smc);
    const int nt = blk % 20, mt = blk / 20;
    const int warp = tid >> 5, lane = tid & 31;
    const int wm = warp >> 2, wn = warp & 3;

    const int arow = wm * 32 + ((lane >> 3) & 1) * 8 + (lane & 7);
    const int achi = (lane >> 4) & 1;
    const uint32_t asw = (uint32_t)((arow >> 1) & 3);
    const uint32_t abase = (uint32_t)(arow * 64);
    const int brow = wn * 32 + ((lane >> 4) & 1) * 8 + (lane & 7);
    const int bclo = (lane >> 3) & 1;
    const uint32_t bsw = (uint32_t)((brow >> 1) & 3);
    const uint32_t bbase = (uint32_t)(brow * 64);

    float acc[8][4];
    #pragma unroll
    for (int i = 0; i < 8; i++) { acc[i][0]=0.f; acc[i][1]=0.f; acc[i][2]=0.f; acc[i][3]=0.f; }

    const __half* Ag = A  + (size_t)(mt * 64) * KP;
    const __half* Bg = Bm + (size_t)(nt * 128) * KP;

    #pragma unroll
    for (int s = 0; s < 3; s++) { qstage_load(sbase, s, Ag, Bg, s * BKC, tid); cp_commit(); }
    cp_wait<2>();
    __syncthreads();

    for (int kt = 0; kt < KITERS; kt++) {
        uint32_t sa = sbase + (kt & 3) * QSTAGE_B;
        uint32_t sb = sa + 4096;

        uint32_t af0[2][4], af1[2][4], bf00[4], bf01[4];
        #pragma unroll
        for (int m = 0; m < 2; m++)
            ldsm_x4(af0[m], sa + abase + m * 1024 + ((((uint32_t)achi) ^ asw) << 4));
        ldsm_x4(bf00, sb + bbase +        ((((uint32_t)bclo) ^ bsw) << 4));
        ldsm_x4(bf01, sb + bbase + 1024 + ((((uint32_t)bclo) ^ bsw) << 4));
        #pragma unroll
        for (int m = 0; m < 2; m++)
            ldsm_x4(af1[m], sa + abase + m * 1024 + ((((uint32_t)(2 + achi)) ^ asw) << 4));

        cp_wait<1>();
        __syncthreads();

        int nxt = kt + 3;
        if (nxt < KITERS) qstage_load(sbase, nxt & 3, Ag, Bg, nxt * BKC, tid);
        cp_commit();

        #pragma unroll
        for (int m = 0; m < 2; m++) {
            mma_16816(acc[m * 4 + 0], af0[m], bf00[0], bf00[1]);
            mma_16816(acc[m * 4 + 1], af0[m], bf00[2], bf00[3]);
            mma_16816(acc[m * 4 + 2], af0[m], bf01[0], bf01[1]);
            mma_16816(acc[m * 4 + 3], af0[m], bf01[2], bf01[3]);
        }
        uint32_t bf10[4], bf11[4];
        ldsm_x4(bf10, sb + bbase +        ((((uint32_t)(2 + bclo)) ^ bsw) << 4));
        ldsm_x4(bf11, sb + bbase + 1024 + ((((uint32_t)(2 + bclo)) ^ bsw) << 4));
        #pragma unroll
        for (int m = 0; m < 2; m++) {
            mma_16816(acc[m * 4 + 0], af1[m], bf10[0], bf10[1]);
            mma_16816(acc[m * 4 + 1], af1[m], bf10[2], bf10[3]);
            mma_16816(acc[m * 4 + 2], af1[m], bf11[0], bf11[1]);
            mma_16816(acc[m * 4 + 3], af1[m], bf11[2], bf11[3]);
        }
    }

    cp_wait<0>();

    // bias add (pre-permuted for Q/K)
    #pragma unroll
    for (int n = 0; n < 4; n++) {
        int col = wn * 32 + n * 8 + (lane & 3) * 2;
        float b0 = bias[nt * 128 + col];
        float b1 = bias[nt * 128 + col + 1];
        #pragma unroll
        for (int m = 0; m < 2; m++) {
            acc[m*4+n][0] += b0; acc[m*4+n][1] += b1;
            acc[m*4+n][2] += b0; acc[m*4+n][3] += b1;
        }
    }

    if (nt >= 18) {
        int kh = nt - 18;
        #pragma unroll
        for (int m = 0; m < 2; m++) {
            int t0 = mt * 64 + wm * 32 + m * 16 + (lane >> 2);
            int b0g = t0 >> 10, s0g = t0 & 1023;
            float mv0 = mask[t0], mv1 = mask[t0 + 8];
            __half* vp0 = Vpk + ((size_t)(b0g * NKV_ + kh) * S_ + s0g) * 128;
            __half* vp1 = vp0 + 8 * 128;
            #pragma unroll
            for (int n = 0; n < 4; n++) {
                int col = wn * 32 + n * 8 + (lane & 3) * 2;
                *(__half2*)(vp0 + col) = __floats2half2_rn(acc[m*4+n][0] * mv0, acc[m*4+n][1] * mv0);
                *(__half2*)(vp1 + col) = __floats2half2_rn(acc[m*4+n][2] * mv1, acc[m*4+n][3] * mv1);
            }
        }
        return;
    }

    const bool isQ = (nt < 16);
    const float* gamma = isQ ? q_gamma : k_gamma;
    int hh = isQ ? nt : (nt - 16);

    #pragma unroll
    for (int m = 0; m < 2; m++) {
        float a0 = 0.f, a1 = 0.f;
        #pragma unroll
        for (int n = 0; n < 4; n++) {
            a0 += acc[m*4+n][0]*acc[m*4+n][0] + acc[m*4+n][1]*acc[m*4+n][1];
            a1 += acc[m*4+n][2]*acc[m*4+n][2] + acc[m*4+n][3]*acc[m*4+n][3];
        }
        a0 += __shfl_xor_sync(0xffffffffu, a0, 1);
        a0 += __shfl_xor_sync(0xffffffffu, a0, 2);
        a1 += __shfl_xor_sync(0xffffffffu, a1, 1);
        a1 += __shfl_xor_sync(0xffffffffu, a1, 2);
        if ((lane & 3) == 0) {
            int r0 = wm * 32 + m * 16 + (lane >> 2);
            ssq[wn][r0]     = a0;
            ssq[wn][r0 + 8] = a1;
        }
    }
    __syncthreads();

    const int dbase = wn * 16 + (lane & 3);
    const int pbase = wn * 32 + (lane & 3) * 2;

    #pragma unroll
    for (int m = 0; m < 2; m++) {
        int r0 = wm * 32 + m * 16 + (lane >> 2);
        int r1 = r0 + 8;
        float rms0 = rsqrtf((ssq[0][r0]+ssq[1][r0]+ssq[2][r0]+ssq[3][r0]) * (1.0f / HD_) + 1e-6f);
        float rms1 = rsqrtf((ssq[0][r1]+ssq[1][r1]+ssq[2][r1]+ssq[3][r1]) * (1.0f / HD_) + 1e-6f);
        int t_0 = mt * 64 + r0;
        int t_1 = t_0 + 8;
        int b0g = t_0 >> 10, s0g = t_0 & 1023;
        int b1g = t_1 >> 10, s1g = t_1 & 1023;
        float mv0 = 1.f, mv1 = 1.f;
        __half *out0, *out1;
        if (isQ) {
            out0 = Qpk + ((size_t)(b0g * NH_ + hh) * S_ + s0g) * 128;
            out1 = Qpk + ((size_t)(b1g * NH_ + hh) * S_ + s1g) * 128;
        } else {
            mv0 = mask[t_0]; mv1 = mask[t_1];
            out0 = Kpk + ((size_t)(b0g * NKV_ + hh) * S_ + s0g) * 128;
            out1 = Kpk + ((size_t)(b1g * NKV_ + hh) * S_ + s1g) * 128;
        }
        #pragma unroll
        for (int n = 0; n < 4; n++) {
            int d = dbase + n * 4;
            int sec = (d < 16) ? 0 : (d < 40) ? 1 : 2;
            float g0 = gamma[d], g1 = gamma[d + 64];
            size_t ci0 = (((size_t)sec * B_ + b0g) * S_ + s0g) * HD_ + d;
            size_t ci1 = (((size_t)sec * B_ + b1g) * S_ + s1g) * HD_ + d;
            int idx = m * 4 + n;
            int p = pbase + n * 8;

            float nvA = acc[idx][0] * rms0 * g0;
            float nvB = acc[idx][1] * rms0 * g1;
            float o0 = nvA * cosb[ci0]      - nvB * sinb[ci0];
            float o1 = nvB * cosb[ci0 + 64] + nvA * sinb[ci0 + 64];
            *(__half2*)(out0 + p) = __floats2half2_rn(o0 * mv0, o1 * mv0);

            nvA = acc[idx][2] * rms1 * g0;
            nvB = acc[idx][3] * rms1 * g1;
            o0 = nvA * cosb[ci1]      - nvB * sinb[ci1];
            o1 = nvB * cosb[ci1 + 64] + nvA * sinb[ci1 + 64];
            *(__half2*)(out1 + p) = __floats2half2_rn(o0 * mv1, o1 * mv1);
        }
    }
}

// ---------------- tensor-core flash attention (unchanged) ----------------
#define ATTN_SMEM 81920

__global__ void __launch_bounds__(128, 2) attn_tc_kernel(
    const __half* __restrict__ Qpk, const __half* __restrict__ Kpk,
    const __half* __restrict__ Vpk, const float* __restrict__ eff,
    __half* __restrict__ Apk)
{
    extern __shared__ char smc[];
    uint32_t sbase = smem_u32(smc);

    int bid = blockIdx.x;
    int qt = 15 - (bid >> 5);
    int rem = bid & 31;
    int h = rem >> 1, b = rem & 1;
    int kvh = h / G_;
    int tid = threadIdx.x, warp = tid >> 5, lane = tid & 31;

    const __half* Qg = Qpk + ((size_t)(b * NH_ + h) * S_ + qt * 64) * 128;
    const __half* Kg = Kpk + ((size_t)(b * NKV_ + kvh) * S_) * 128;
    const __half* Vg = Vpk + ((size_t)(b * NKV_ + kvh) * S_) * 128;

    #pragma unroll
    for (int it = 0; it < 8; it++) {
        int idx = it * 128 + tid;
        int r = idx >> 4, c = idx & 15;
        cp_async16(sbase + r * 256 + csw8(c, r) * 16, Qg + (size_t)r * 128 + c * 8);
    }
    cp_commit();
    cp_wait<0>();
    __syncthreads();

    uint32_t qh[8][4];
    {
        int row = warp * 16 + ((lane >> 3) & 1) * 8 + (lane & 7);
        uint32_t roff = sbase + row * 256;
        uint32_t r7 = row & 7;
        int chi = (lane >> 4) & 1;
        #pragma unroll
        for (int j = 0; j < 8; j++) {
            uint32_t ch = 2 * j + chi;
            ldsm_x4(qh[j], roff + ((ch & 8u) | ((ch ^ r7) & 7u)) * 16);
        }
    }

    int ntiles = qt + 1;
    int eff_i = (int)(eff[b] + 0.5f);

    #pragma unroll
    for (int pt = 0; pt < 2; pt++) {
        if (pt < ntiles) {
            #pragma unroll
            for (int it = 0; it < 8; it++) {
                int idx = it * 128 + tid;
                int r = idx >> 4, c = idx & 15;
                uint32_t ds = 16384u + (uint32_t)pt * 32768 + r * 256 + csw8(c, r) * 16;
                size_t go = (size_t)(pt * 64 + r) * 128 + c * 8;
                cp_async16(sbase + ds,         Kg + go);
                cp_async16(sbase + ds + 16384, Vg + go);
            }
        }
        cp_commit();
    }

    float m0 = -1e30f, m1 = -1e30f, ls0 = 0.f, ls1 = 0.f;
    float o[16][4];
    #pragma unroll
    for (int i = 0; i < 16; i++) { o[i][0] = o[i][1] = o[i][2] = o[i][3] = 0.f; }

    const float scale = 0.08838834764831845f;
    int row0 = qt * 64 + warp * 16 + (lane >> 2);
    int colb = (lane & 3) * 2;
    int krbase = ((lane >> 4) & 1) * 8 + (lane & 7);
    int kchi = (lane >> 3) & 1;
    int vrbase = ((lane >> 3) & 1) * 8 + (lane & 7);
    int vchi = (lane >> 4) & 1;

    for (int kt = 0; kt < ntiles; kt++) {
        cp_wait<1>();
        __syncthreads();
        uint32_t sk = sbase + 16384u + (uint32_t)(kt & 1) * 32768;
        uint32_t sv = sk + 16384;

        float s[8][4];
        #pragma unroll
        for (int i = 0; i < 8; i++) { s[i][0] = s[i][1] = s[i][2] = s[i][3] = 0.f; }

        #pragma unroll
        for (int nbp = 0; nbp < 4; nbp++) {
            int krow = nbp * 16 + krbase;
            uint32_t kroff = sk + krow * 256;
            uint32_t kr7 = krow & 7;
            #pragma unroll
            for (int j = 0; j < 8; j++) {
                uint32_t ch = 2 * j + kchi;
                uint32_t kf[4];
                ldsm_x4(kf, kroff + ((ch & 8u) | ((ch ^ kr7) & 7u)) * 16);
                mma_16816(s[2*nbp],   qh[j], kf[0], kf[1]);
                mma_16816(s[2*nbp+1], qh[j], kf[2], kf[3]);
            }
        }

        float mx0 = -1e30f, mx1 = -1e30f;
        #pragma unroll
        for (int nb = 0; nb < 8; nb++) {
            int c0 = kt * 64 + nb * 8 + colb;
            #pragma unroll
            for (int e = 0; e < 2; e++) {
                int cc = c0 + e;
                float v0 = (cc <= row0     && cc < eff_i) ? s[nb][e]   * scale : -1e9f;
                float v1 = (cc <= row0 + 8 && cc < eff_i) ? s[nb][2+e] * scale : -1e9f;
                s[nb][e] = v0; s[nb][2+e] = v1;
                mx0 = fmaxf(mx0, v0); mx1 = fmaxf(mx1, v1);
            }
        }
        mx0 = fmaxf(mx0, __shfl_xor_sync(0xffffffffu, mx0, 1));
        mx0 = fmaxf(mx0, __shfl_xor_sync(0xffffffffu, mx0, 2));
        mx1 = fmaxf(mx1, __shfl_xor_sync(0xffffffffu, mx1, 1));
        mx1 = fmaxf(mx1, __shfl_xor_sync(0xffffffffu, mx1, 2));
        float m0n = fmaxf(m0, mx0), m1n = fmaxf(m1, mx1);
        float cr0 = __expf(m0 - m0n), cr1 = __expf(m1 - m1n);
        float sum0 = 0.f, sum1 = 0.f;
        #pragma unroll
        for (int nb = 0; nb < 8; nb++) {
            #pragma unroll
            for (int e = 0; e < 2; e++) {
                float p0 = __expf(s[nb][e]   - m0n);
                float p1 = __expf(s[nb][2+e] - m1n);
                s[nb][e] = p0; s[nb][2+e] = p1;
                sum0 += p0; sum1 += p1;
            }
        }
        sum0 += __shfl_xor_sync(0xffffffffu, sum0, 1);
        sum0 += __shfl_xor_sync(0xffffffffu, sum0, 2);
        sum1 += __shfl_xor_sync(0xffffffffu, sum1, 1);
        sum1 += __shfl_xor_sync(0xffffffffu, sum1, 2);
        ls0 = ls0 * cr0 + sum0; m0 = m0n;
        ls1 = ls1 * cr1 + sum1; m1 = m1n;
        #pragma unroll
        for (int i = 0; i < 16; i++) {
            o[i][0] *= cr0; o[i][1] *= cr0;
            o[i][2] *= cr1; o[i][3] *= cr1;
        }

        uint32_t ph[4][4];
        #pragma unroll
        for (int j2 = 0; j2 < 4; j2++) {
            #pragma unroll
            for (int q = 0; q < 4; q++) {
                int nb = 2 * j2 + (q >> 1);
                int e  = (q & 1) * 2;
                unsigned short ha = __half_as_ushort(__float2half_rn(s[nb][e]));
                unsigned short hb = __half_as_ushort(__float2half_rn(s[nb][e + 1]));
                ph[j2][(q >> 1) * 2 + (q & 1)] = pack2(ha, hb);
            }
        }

        #pragma unroll
        for (int j2 = 0; j2 < 4; j2++) {
            int vrow = j2 * 16 + vrbase;
            uint32_t vroff = sv + vrow * 256;
            uint32_t vr7 = vrow & 7;
            #pragma unroll
            for (int nbp = 0; nbp < 8; nbp++) {
                uint32_t ch = 2 * nbp + vchi;
                uint32_t vf[4];
                ldsm_x4_t(vf, vroff + ((ch & 8u) | ((ch ^ vr7) & 7u)) * 16);
                mma_16816(o[2*nbp],   ph[j2], vf[0], vf[1]);
                mma_16816(o[2*nbp+1], ph[j2], vf[2], vf[3]);
            }
        }

        __syncthreads();
        int nxt = kt + 2;
        if (nxt < ntiles) {
            #pragma unroll
            for (int it = 0; it < 8; it++) {
                int idx = it * 128 + tid;
                int r = idx >> 4, c = idx & 15;
                uint32_t ds = 16384u + (uint32_t)(kt & 1) * 32768 + r * 256 + csw8(c, r) * 16;
                size_t go = (size_t)(nxt * 64 + r) * 128 + c * 8;
                cp_async16(sbase + ds,         Kg + go);
                cp_async16(sbase + ds + 16384, Vg + go);
            }
        }
        cp_commit();
    }

    float inv0 = 1.0f / ls0, inv1 = 1.0f / ls1;
    int t0 = b * S_ + qt * 64 + warp * 16 + (lane >> 2);
    size_t r0b = (size_t)t0 * KP;
    size_t r1b = (size_t)(t0 + 8) * KP;
    #pragma unroll
    for (int db = 0; db < 16; db++) {
        int c = h * 128 + db * 8 + colb;
        __half h0 = __float2half_rn(o[db][0] * inv0);
        __half h1 = __float2half_rn(o[db][1] * inv0);
        *(uint32_t*)(Apk + r0b + c) = pack2(__half_as_ushort(h0), __half_as_ushort(h1));
        h0 = __float2half_rn(o[db][2] * inv1);
        h1 = __float2half_rn(o[db][3] * inv1);
        *(uint32_t*)(Apk + r1b + c) = pack2(__half_as_ushort(h0), __half_as_ushort(h1));
    }
}

// ---------------- launcher ----------------
extern "C" void kernel_launch(void* const* d_in, const int* in_sizes, int n_in,
                              void* d_out, int out_size)
{
    const float* x       = (const float*)d_in[0];
    const float* cosb    = (const float*)d_in[1];
    const float* sinb    = (const float*)d_in[2];
    const float* mask    = (const float*)d_in[3];
    const float* q_w     = (const float*)d_in[4];
    const float* q_b     = (const float*)d_in[5];
    const float* k_w     = (const float*)d_in[6];
    const float* k_b     = (const float*)d_in[7];
    const float* v_w     = (const float*)d_in[8];
    const float* v_b     = (const float*)d_in[9];
    const float* q_gamma = (const float*)d_in[10];
    const float* k_gamma = (const float*)d_in[11];
    const float* o_w     = (const float*)d_in[12];
    float* out = (float*)d_out;

    float* scratch = nullptr;
    cudaGetSymbolAddress((void**)&scratch, g_scratch);
    float* geff = scratch + OFF_EFF;
    float* bias = scratch + OFF_BIAS;
    __half* Apack = (__half*)(scratch + OFF_APK);
    __half* Bqkv  = (__half*)(scratch + OFF_BQKV);
    __half* Bow   = (__half*)(scratch + OFF_BOW);
    __half* Qpk   = (__half*)(scratch + OFF_QPK);
    __half* Kpk   = (__half*)(scratch + OFF_KPK);
    __half* Vpk   = (__half*)(scratch + OFF_VPK);

    cudaFuncSetAttribute(gemm_mma_kernel, cudaFuncAttributeMaxDynamicSharedMemorySize, GEMM_SMEM);
    cudaFuncSetAttribute(gemm_qkv_fused,  cudaFuncAttributeMaxDynamicSharedMemorySize, QKV_SMEM);
    cudaFuncSetAttribute(attn_tc_kernel,  cudaFuncAttributeMaxDynamicSharedMemorySize, ATTN_SMEM);

    conv_all_kernel<<<2048 + CONVB_BLKS + 12, 256>>>(
        x, q_w, k_w, v_w, mask, q_b, k_b, v_b,
        Apack, Bqkv, geff, bias);
    gemm_qkv_fused<<<QKV_GEMM_BLKS + OW_UNITS, 256, QKV_SMEM>>>(
        Apack, Bqkv, bias, cosb, sinb, mask, q_gamma, k_gamma,
        o_w, Bow, Qpk, Kpk, Vpk);
    attn_tc_kernel<<<512, 128, ATTN_SMEM>>>(Qpk, Kpk, Vpk, geff, Apack);
    gemm_mma_kernel<<<dim3(16, 16), 256, GEMM_SMEM>>>(Apack, Bow, out, 2048);
}